// round 12
// baseline (speedup 1.0000x reference)
#include <cuda_runtime.h>

#define NQ 9
#define HOUT 128
#define WOUT 128
#define HW 384
#define PLANE (HOUT * WOUT)

// Final kernel (R7 structure, measured best: 6.62 us total / 4.48 us kernel).
//
// Math: the 9-qubit product-state circuit collapses analytically.
//   - per qubit: <Z> after Rx(a2)Rz(a1)Rx(a0) on Ry(pi*x)|0> is
//         z = A*sin(pi x) + B*cos(pi x) = R * sin(pi x + phi)
//   - the CNOT-ring permutation + sign matrix reduce each output channel to
//     a product of per-qubit z's: plane j>=1 = prod z0..zj, plane 0 = z1..z8.
//
// Structure: 1 thread = one 3x3 window; warp-autonomous (no smem, no block
// barriers). The 9 window loads are issued first and stay in flight while
// each warp rebuilds the 9 (R, phi) constants from the 27 weights
// (__sincosf on lanes 0-26, combine on lanes 0-8, sqrtf/atan2f, then 18
// hoisted shuffle broadcasts). Per pixel: FMA + MUFU sin + FMUL.
__global__ void __launch_bounds__(256) quanconv_fused(
    const float* __restrict__ in, const float* __restrict__ w,
    float* __restrict__ out) {

    const unsigned FULL = 0xFFFFFFFFu;
    const int tid  = threadIdx.x;
    const int lane = tid & 31;
    const int gid  = blockIdx.x * 256 + tid;    // 0..65535 windows
    const int wo = gid & (WOUT - 1);
    const int ho = (gid >> 7) & (HOUT - 1);
    const int b  = gid >> 14;

    // ---- weight load first (tiny, L2-hot) ----
    const float M = 0.63245553203367586640f;    // sqrt(2/5) = W_MUL
    float ww = __ldg(w + (lane < 27 ? lane : 26)) * M;

    // ---- issue all 9 window loads (independent, in flight together) ----
    const float* base = in + (b * HW + ho * 3) * HW + wo * 3;
    float x[NQ];
#pragma unroll
    for (int kr = 0; kr < 3; kr++)
#pragma unroll
        for (int kc = 0; kc < 3; kc++)
            x[kr * 3 + kc] = __ldg(base + kr * HW + kc);

    // ---- per-warp setup (overlaps the loads above) ----
    float s, c;
    __sincosf(ww, &s, &c);
    float s0 = __shfl_sync(FULL, s, 3 * lane);
    float c0 = __shfl_sync(FULL, c, 3 * lane);
    float s1 = __shfl_sync(FULL, s, 3 * lane + 1);
    float c1 = __shfl_sync(FULL, c, 3 * lane + 1);
    float s2 = __shfl_sync(FULL, s, 3 * lane + 2);
    float c2 = __shfl_sync(FULL, c, 3 * lane + 2);
    float A = s1 * s2;
    float B = fmaf(c0, c2, -(s0 * c1 * s2));
    float Rv  = sqrtf(fmaf(A, A, B * B));
    float Phi = atan2f(B, A);                   // lanes 0..8 meaningful

    // hoisted broadcasts: every lane gets all 9 (R, phi) pairs
    float Rq[NQ], Pq[NQ];
#pragma unroll
    for (int q = 0; q < NQ; q++) {
        Rq[q] = __shfl_sync(FULL, Rv,  q);
        Pq[q] = __shfl_sync(FULL, Phi, q);
    }

    // ---- per-pixel: z = R * sin(pi*x + phi)  (waits on x loads) ----
    const float PI_F = 3.14159274101257324219f;
    float z[NQ];
#pragma unroll
    for (int q = 0; q < NQ; q++)
        z[q] = Rq[q] * __sinf(fmaf(PI_F, x[q], Pq[q]));

    // prefixes p_j = z0..zj are outputs 1..8; output 0 = z1..z8 (suffix)
    float p1 = z[0] * z[1];
    float p2 = p1 * z[2];
    float p3 = p2 * z[3];
    float p4 = p3 * z[4];
    float p5 = p4 * z[5];
    float p6 = p5 * z[6];
    float p7 = p6 * z[7];
    float p8 = p7 * z[8];
    float suf = ((z[1] * z[2]) * (z[3] * z[4])) *
                ((z[5] * z[6]) * (z[7] * z[8]));

    float* obase = out + b * (NQ * PLANE) + ho * WOUT + wo;
    obase[0 * PLANE] = suf;
    obase[1 * PLANE] = p1;
    obase[2 * PLANE] = p2;
    obase[3 * PLANE] = p3;
    obase[4 * PLANE] = p4;
    obase[5 * PLANE] = p5;
    obase[6 * PLANE] = p6;
    obase[7 * PLANE] = p7;
    obase[8 * PLANE] = p8;
}

extern "C" void kernel_launch(void* const* d_in, const int* in_sizes, int n_in,
                              void* d_out, int out_size) {
    const float* x = (const float*)d_in[0];   // (4,1,384,384) float32
    const float* w = (const float*)d_in[1];   // (27,) float32
    float* out = (float*)d_out;               // (4,9,128,128) float32

    quanconv_fused<<<65536 / 256, 256>>>(x, w, out);
}

// round 13
// speedup vs baseline: 1.0435x; 1.0435x over previous
#include <cuda_runtime.h>

#define NQ 9
#define HOUT 128
#define WOUT 128
#define HW 384
#define PLANE (HOUT * WOUT)

// FINAL kernel (R7 structure; best measured total 6.62 us, kernel 4.48 us;
// run-to-run noise +/-0.3 us — R4/R5/R9/R11/R12 variants all within noise).
//
// Math: the 9-qubit product-state circuit collapses analytically.
//   - per qubit: <Z> after Rx(a2)Rz(a1)Rx(a0) on Ry(pi*x)|0> is
//         z = A*sin(pi x) + B*cos(pi x) = R * sin(pi x + phi)
//     with A = sin(a1)sin(a2), B = cos(a0)cos(a2) - sin(a0)cos(a1)sin(a2).
//   - the CNOT-ring permutation is GF(2)-linear; each output channel is the
//     expectation of a parity, which factorizes over qubits:
//         plane j>=1 = prod_{q<=j} z_q ,  plane 0 = prod_{q=1..8} z_q.
//
// Structure: 1 thread = one 3x3 window; warp-autonomous (no smem, no block
// barriers). The 9 window loads are issued first and stay in flight while
// each warp rebuilds the 9 (R, phi) constants from the 27 weights
// (__sincosf on lanes 0-26, combine on lanes 0-8, sqrtf/atan2f, then 18
// hoisted shuffle broadcasts). Per pixel: FMA + RRO/MUFU.SIN + FMUL.
//
// Perf model (settled over R4-R12): no pipe exceeds 7%; time = launch ramp
// (~5000 cyc) + one exposed L2-latency chain + fixed harness replay gap.
__global__ void __launch_bounds__(256) quanconv_fused(
    const float* __restrict__ in, const float* __restrict__ w,
    float* __restrict__ out) {

    const unsigned FULL = 0xFFFFFFFFu;
    const int tid  = threadIdx.x;
    const int lane = tid & 31;
    const int gid  = blockIdx.x * 256 + tid;    // 0..65535 windows
    const int wo = gid & (WOUT - 1);
    const int ho = (gid >> 7) & (HOUT - 1);
    const int b  = gid >> 14;

    // ---- weight load first (tiny, L2-hot) ----
    const float M = 0.63245553203367586640f;    // sqrt(2/5) = W_MUL
    float ww = __ldg(w + (lane < 27 ? lane : 26)) * M;

    // ---- issue all 9 window loads (independent, in flight together) ----
    const float* base = in + (b * HW + ho * 3) * HW + wo * 3;
    float x[NQ];
#pragma unroll
    for (int kr = 0; kr < 3; kr++)
#pragma unroll
        for (int kc = 0; kc < 3; kc++)
            x[kr * 3 + kc] = __ldg(base + kr * HW + kc);

    // ---- per-warp setup (overlaps the loads above) ----
    float s, c;
    __sincosf(ww, &s, &c);
    float s0 = __shfl_sync(FULL, s, 3 * lane);
    float c0 = __shfl_sync(FULL, c, 3 * lane);
    float s1 = __shfl_sync(FULL, s, 3 * lane + 1);
    float c1 = __shfl_sync(FULL, c, 3 * lane + 1);
    float s2 = __shfl_sync(FULL, s, 3 * lane + 2);
    float c2 = __shfl_sync(FULL, c, 3 * lane + 2);
    float A = s1 * s2;
    float B = fmaf(c0, c2, -(s0 * c1 * s2));
    float Rv  = sqrtf(fmaf(A, A, B * B));
    float Phi = atan2f(B, A);                   // lanes 0..8 meaningful

    // hoisted broadcasts: every lane gets all 9 (R, phi) pairs
    float Rq[NQ], Pq[NQ];
#pragma unroll
    for (int q = 0; q < NQ; q++) {
        Rq[q] = __shfl_sync(FULL, Rv,  q);
        Pq[q] = __shfl_sync(FULL, Phi, q);
    }

    // ---- per-pixel: z = R * sin(pi*x + phi)  (waits on x loads) ----
    const float PI_F = 3.14159274101257324219f;
    float z[NQ];
#pragma unroll
    for (int q = 0; q < NQ; q++)
        z[q] = Rq[q] * __sinf(fmaf(PI_F, x[q], Pq[q]));

    // prefixes p_j = z0..zj are outputs 1..8; output 0 = z1..z8 (suffix)
    float p1 = z[0] * z[1];
    float p2 = p1 * z[2];
    float p3 = p2 * z[3];
    float p4 = p3 * z[4];
    float p5 = p4 * z[5];
    float p6 = p5 * z[6];
    float p7 = p6 * z[7];
    float p8 = p7 * z[8];
    float suf = ((z[1] * z[2]) * (z[3] * z[4])) *
                ((z[5] * z[6]) * (z[7] * z[8]));

    float* obase = out + b * (NQ * PLANE) + ho * WOUT + wo;
    obase[0 * PLANE] = suf;
    obase[1 * PLANE] = p1;
    obase[2 * PLANE] = p2;
    obase[3 * PLANE] = p3;
    obase[4 * PLANE] = p4;
    obase[5 * PLANE] = p5;
    obase[6 * PLANE] = p6;
    obase[7 * PLANE] = p7;
    obase[8 * PLANE] = p8;
}

extern "C" void kernel_launch(void* const* d_in, const int* in_sizes, int n_in,
                              void* d_out, int out_size) {
    const float* x = (const float*)d_in[0];   // (4,1,384,384) float32
    const float* w = (const float*)d_in[1];   // (27,) float32
    float* out = (float*)d_out;               // (4,9,128,128) float32

    quanconv_fused<<<65536 / 256, 256>>>(x, w, out);
}